// round 12
// baseline (speedup 1.0000x reference)
#include <cuda_runtime.h>
#include <cstddef>

// ---------------------------------------------------------------------------
//  B=1, C=8, O=8, G=12, X=Y=Z=12, CH=8, CW=40, Xo=Yo=Zo=9, N=729, GO=96, b=7
//  Stage1: t[n][ob][pos] = sum_{c,f} W[o,c,f,b] * x[c, n+f, pos]
//  Stage2: out[g*8+o][voxel][h,w] = bias_sum[o]
//            + sum_{b,u,v} basis[T[g,h,w], b,u,v] * t[n][o*7+b][(I-1+u)*40 + (J-1+v)]
// ---------------------------------------------------------------------------

typedef unsigned long long u64;

#define T_ELEMS (729 * 56 * 320)
__device__ __align__(16) float g_t[T_ELEMS];   // 52.25 MB scratch

__device__ __forceinline__ u64 pack2(float a, float b) {
    u64 r;
    asm("mov.b64 %0, {%1, %2};" : "=l"(r) : "f"(a), "f"(b));
    return r;
}
__device__ __forceinline__ void unpack2(u64 v, float& a, float& b) {
    asm("mov.b64 {%0, %1}, %2;" : "=f"(a), "=f"(b) : "l"(v));
}
__device__ __forceinline__ void ffma2(u64& acc, u64 w, u64 x) {
    asm("fma.rn.f32x2 %0, %1, %2, %0;" : "+l"(acc) : "l"(w), "l"(x));
}

// ---------------------------------------------------------------------------
// Stage 1: one CTA per n (729). 320 threads, one position each.
// Weights in shared as [f][c][ob] (128-bit broadcast reads). x prefetched
// 8 channels at a time (MLP=8) to hide L2 latency. 28 f32x2 accumulators.
// ---------------------------------------------------------------------------
__global__ void __launch_bounds__(320, 2)
stage1_kernel(const float* __restrict__ x, const float* __restrict__ weight)
{
    __shared__ __align__(16) float Wsh[12096];   // [(f*8+c)*56 + o*7 + b]
    __shared__ int off_sh[27];

    const int n   = blockIdx.x;
    const int tid = threadIdx.x;

    // transpose weight: (o,c,f,b) -> [(f*8+c)*56 + o*7 + b]
    for (int i = tid; i < 12096; i += 320) {
        int o = i / 1512;  int r = i - o * 1512;
        int c = r / 189;   r -= c * 189;
        int f = r / 7;     int b = r - f * 7;
        Wsh[(f * 8 + c) * 56 + o * 7 + b] = weight[i];
    }
    if (tid < 27) {
        int fi = tid / 9;  int fr = tid - fi * 9;
        int fj = fr / 3;   int fk = fr - fj * 3;
        off_sh[tid] = fi * 46080 + fj * 3840 + fk * 320;
    }
    __syncthreads();

    const int zi = n % 9;
    const int yi = (n / 9) % 9;
    const int xi = n / 81;
    const float* xb = x + (size_t)xi * 46080 + (size_t)yi * 3840 + (size_t)zi * 320 + tid;

    u64 acc[28];
#pragma unroll
    for (int p = 0; p < 28; p++) acc[p] = 0ull;

    float cur[8];
#pragma unroll
    for (int c = 0; c < 8; c++) cur[c] = xb[c * 552960];   // off_sh[0] == 0

    for (int f = 0; f < 27; f++) {
        float nxt[8];
#pragma unroll
        for (int c = 0; c < 8; c++) nxt[c] = 0.f;
        if (f + 1 < 27) {
            const int o1 = off_sh[f + 1];
#pragma unroll
            for (int c = 0; c < 8; c++) nxt[c] = xb[o1 + c * 552960];
        }

#pragma unroll
        for (int c = 0; c < 8; c++) {
            u64 xx = pack2(cur[c], cur[c]);
            const ulonglong2* wp = (const ulonglong2*)(Wsh + (f * 8 + c) * 56);
#pragma unroll
            for (int p = 0; p < 14; p++) {
                ulonglong2 ww = wp[p];
                ffma2(acc[2 * p],     ww.x, xx);
                ffma2(acc[2 * p + 1], ww.y, xx);
            }
        }
#pragma unroll
        for (int c = 0; c < 8; c++) cur[c] = nxt[c];
    }

    float* tp = g_t + (size_t)n * 17920 + tid;
#pragma unroll
    for (int q = 0; q < 28; q++) {
        float lo, hi;
        unpack2(acc[q], lo, hi);
        tp[(2 * q) * 320]     = lo;   // ob = 2q
        tp[(2 * q + 1) * 320] = hi;   // ob = 2q+1
    }
}

// ---------------------------------------------------------------------------
// Stage 2: one CTA per output voxel (1728), 640 threads.
// Thread = (og, hh, w): og=tid/160 -> o in {2og, 2og+1}; hh -> row pair
// (2hh, 2hh+1); w=0..39. Position pair packed into f32x2 accumulators:
// FMA instruction count halved. g in 3 chunks of 4; basis in shared with
// stride-12 rows for aligned float4 loads. ~90 regs, no spills.
// ---------------------------------------------------------------------------
__global__ void __launch_bounds__(640, 1)
stage2_kernel(const float* __restrict__ basis, const float* __restrict__ bias,
              const int* __restrict__ Iarr, const int* __restrict__ Jarr,
              const int* __restrict__ Tarr, float* __restrict__ out)
{
    extern __shared__ float tsh[];                 // 17920 floats = 71680 B
    __shared__ __align__(16) float bas_sh[1008];   // [tg][b][12] padded
    __shared__ float bias_sh[8];

    const int v   = blockIdx.x;
    const int tid = threadIdx.x;
    const int zv  = v % 12;
    const int yv  = (v / 12) % 12;
    const int xv  = v / 144;

    if (xv < 1 || xv > 9 || yv < 1 || yv > 9 || zv < 1 || zv > 9) {
        const float4 z = make_float4(0.f, 0.f, 0.f, 0.f);
        for (int i = tid; i < 7680; i += 640) {
            int go = i / 80;
            int r  = i - go * 80;
            float4* p = (float4*)(out + (size_t)go * 552960 + (size_t)v * 320);
            p[r] = z;
        }
        return;
    }

    const int n = (xv - 1) * 81 + (yv - 1) * 9 + (zv - 1);

    {
        const float4* src = (const float4*)(g_t + (size_t)n * 17920);
        float4* dst = (float4*)tsh;
        for (int i = tid; i < 4480; i += 640) dst[i] = src[i];
    }
    // basis re-layout: [g][b][12] (rows padded 9->12 for aligned float4)
    for (int i = tid; i < 1008; i += 640) {
        int g = i / 84;  int r = i - g * 84;
        int b = r / 12;  int j = r - b * 12;
        bas_sh[i] = (j < 9) ? basis[g * 63 + b * 9 + j] : 0.f;
    }
    if (tid < 8) {
        float s = 0.f;
        for (int j = 0; j < 27; j++) s += bias[tid * 27 + j];
        bias_sh[tid] = s;
    }
    __syncthreads();

    const int og  = tid / 160;          // 0..3 -> o pair base
    const int rem = tid - og * 160;
    const int hh  = rem / 40;           // 0..3 -> rows (2hh, 2hh+1)
    const int w   = rem - hh * 40;      // 0..39
    const int o0  = og * 2;
    const int p0  = hh * 80 + w;
    const int p1  = p0 + 40;

    const int jw = Jarr[p0] - 1;        // 0..37
    const int I0 = Iarr[p0];
    const int I1 = Iarr[p1];
    const int su = I1 - I0;             // 0 or 1
    const int r0 = I0 - 1;

    int rro[4];
#pragma unroll
    for (int j = 0; j < 4; j++) {
        int rr = r0 + j;
        if (rr > 7) rr = 7;             // only reachable when unused (su==0)
        rro[j] = rr * 40 + jw;
    }

    float* op0 = out + (size_t)v * 320 + p0;

    for (int gc = 0; gc < 3; gc++) {
        int tg0[4], tg1[4];
#pragma unroll
        for (int gg = 0; gg < 4; gg++) {
            int g = gc * 4 + gg;
            tg0[gg] = Tarr[g * 320 + p0];
            tg1[gg] = Tarr[g * 320 + p1];
        }

        u64 acc[4][2];
#pragma unroll
        for (int gg = 0; gg < 4; gg++) { acc[gg][0] = 0ull; acc[gg][1] = 0ull; }

#pragma unroll 1
        for (int b = 0; b < 7; b++) {
            // position-pair packed windows for both o values
            u64 wpack[2][9];
#pragma unroll
            for (int oo = 0; oo < 2; oo++) {
                const float* tb = tsh + ((o0 + oo) * 7 + b) * 320;
                float win[4][3];
#pragma unroll
                for (int j = 0; j < 4; j++)
#pragma unroll
                    for (int vv = 0; vv < 3; vv++)
                        win[j][vv] = tb[rro[j] + vv];
#pragma unroll
                for (int u = 0; u < 3; u++)
#pragma unroll
                    for (int vv = 0; vv < 3; vv++) {
                        float s = su ? win[u + 1][vv] : win[u][vv];
                        wpack[oo][u * 3 + vv] = pack2(win[u][vv], s);
                    }
            }

#pragma unroll
            for (int gg = 0; gg < 4; gg++) {
                const float* q0 = bas_sh + tg0[gg] * 84 + b * 12;
                const float* q1 = bas_sh + tg1[gg] * 84 + b * 12;
                float4 a0 = ((const float4*)q0)[0];
                float4 b0 = ((const float4*)q0)[1];
                float  c0 = q0[8];
                float4 a1 = ((const float4*)q1)[0];
                float4 b1 = ((const float4*)q1)[1];
                float  c1 = q1[8];
                u64 bgp[9];
                bgp[0] = pack2(a0.x, a1.x);
                bgp[1] = pack2(a0.y, a1.y);
                bgp[2] = pack2(a0.z, a1.z);
                bgp[3] = pack2(a0.w, a1.w);
                bgp[4] = pack2(b0.x, b1.x);
                bgp[5] = pack2(b0.y, b1.y);
                bgp[6] = pack2(b0.z, b1.z);
                bgp[7] = pack2(b0.w, b1.w);
                bgp[8] = pack2(c0, c1);
#pragma unroll
                for (int oo = 0; oo < 2; oo++)
#pragma unroll
                    for (int i = 0; i < 9; i++)
                        ffma2(acc[gg][oo], bgp[i], wpack[oo][i]);
            }
        }

#pragma unroll
        for (int gg = 0; gg < 4; gg++) {
            int g = gc * 4 + gg;
#pragma unroll
            for (int oo = 0; oo < 2; oo++) {
                int o = o0 + oo;
                float lo, hi;
                unpack2(acc[gg][oo], lo, hi);
                float bs = bias_sh[o];
                float* dst = op0 + (size_t)(g * 8 + o) * 552960;
                dst[0]  = lo + bs;
                dst[40] = hi + bs;
            }
        }
    }
}

// ---------------------------------------------------------------------------
extern "C" void kernel_launch(void* const* d_in, const int* in_sizes, int n_in,
                              void* d_out, int out_size)
{
    (void)in_sizes; (void)n_in; (void)out_size;

    const float* x      = (const float*)d_in[0];
    const float* weight = (const float*)d_in[1];
    const float* bias   = (const float*)d_in[2];
    const float* basis  = (const float*)d_in[3];
    const int*   Iarr   = (const int*)d_in[4];
    const int*   Jarr   = (const int*)d_in[5];
    const int*   Tarr   = (const int*)d_in[6];
    float*       out    = (float*)d_out;

    cudaFuncSetAttribute(stage2_kernel,
                         cudaFuncAttributeMaxDynamicSharedMemorySize, 71680);

    stage1_kernel<<<729, 320>>>(x, weight);
    stage2_kernel<<<1728, 640, 71680>>>(basis, bias, Iarr, Jarr, Tarr, out);
}

// round 15
// speedup vs baseline: 1.2072x; 1.2072x over previous
#include <cuda_runtime.h>
#include <cstddef>

// ---------------------------------------------------------------------------
//  B=1, C=8, O=8, G=12, X=Y=Z=12, CH=8, CW=40, Xo=Yo=Zo=9, N=729, GO=96, b=7
//  Stage1: t[n][ob][pos] = sum_{c,f} W[o,c,f,b] * x[c, n+f, pos]
//  Stage2 (gather-last):
//    accP[g][o][i'][j'] = sum_{b,u,v} basis[g,b,u,v] * t[o*7+b][(i'+u)*40 + j'+v]
//    out[g*8+o][v][h,w] = accP[T[g,h,w]][o][I[h,w]-1][J[h,w]-1] + bias_sum[o]
// ---------------------------------------------------------------------------

typedef unsigned long long u64;

#define T_ELEMS (729 * 56 * 320)
__device__ __align__(16) float g_t[T_ELEMS];   // 52.25 MB scratch

__device__ __forceinline__ u64 pack2(float a, float b) {
    u64 r;
    asm("mov.b64 %0, {%1, %2};" : "=l"(r) : "f"(a), "f"(b));
    return r;
}
__device__ __forceinline__ void unpack2(u64 v, float& a, float& b) {
    asm("mov.b64 {%0, %1}, %2;" : "=f"(a), "=f"(b) : "l"(v));
}
__device__ __forceinline__ void ffma2(u64& acc, u64 w, u64 x) {
    asm("fma.rn.f32x2 %0, %1, %2, %0;" : "+l"(acc) : "l"(w), "l"(x));
}

// ---------------------------------------------------------------------------
// Stage 1 (R10 known-good): one CTA per n (729), 320 threads, one pos each.
// Weights transposed in shared to [c][f][ob], read via 128-bit broadcasts;
// depth-2 scalar x prefetch; 28 f32x2 accumulators.
// ---------------------------------------------------------------------------
__global__ void __launch_bounds__(320, 2)
stage1_kernel(const float* __restrict__ x, const float* __restrict__ weight)
{
    __shared__ __align__(16) float Wsh[12096];   // [c][f][ob]
    __shared__ int off_sh[216];

    const int n   = blockIdx.x;
    const int tid = threadIdx.x;

    for (int i = tid; i < 12096; i += 320) {
        int o = i / 1512;  int r = i - o * 1512;
        int c = r / 189;   r -= c * 189;
        int f = r / 7;     int b = r - f * 7;
        Wsh[(c * 27 + f) * 56 + o * 7 + b] = weight[i];
    }
    if (tid < 216) {
        int c  = tid / 27;  int f  = tid - c * 27;
        int fi = f / 9;     int fr = f - fi * 9;
        int fj = fr / 3;    int fk = fr - fj * 3;
        off_sh[tid] = c * 552960 + fi * 46080 + fj * 3840 + fk * 320;
    }
    __syncthreads();

    const int zi = n % 9;
    const int yi = (n / 9) % 9;
    const int xi = n / 81;
    const float* xb = x + (size_t)xi * 46080 + (size_t)yi * 3840 + (size_t)zi * 320 + tid;

    u64 acc[28];
#pragma unroll
    for (int p = 0; p < 28; p++) acc[p] = 0ull;

    float a_c = xb[0];
    float a_n = xb[off_sh[1]];

    for (int cf = 0; cf < 216; cf++) {
        float a_2 = 0.f;
        if (cf + 2 < 216) a_2 = xb[off_sh[cf + 2]];

        u64 xx = pack2(a_c, a_c);
        const ulonglong2* wp = (const ulonglong2*)(Wsh + cf * 56);
#pragma unroll
        for (int p = 0; p < 14; p++) {
            ulonglong2 ww = wp[p];
            ffma2(acc[2 * p],     ww.x, xx);
            ffma2(acc[2 * p + 1], ww.y, xx);
        }
        a_c = a_n;
        a_n = a_2;
    }

    float* tp = g_t + (size_t)n * 17920 + tid;
#pragma unroll
    for (int q = 0; q < 28; q++) {
        float lo, hi;
        unpack2(acc[q], lo, hi);
        tp[(2 * q) * 320]     = lo;
        tp[(2 * q + 1) * 320] = hi;
    }
}

// ---------------------------------------------------------------------------
// Stage 2 (gather-last): grid = 1728 voxels x 2 o-halves, 480 threads.
// Phase A (dense): thread = (oo 0..3, q 0..2, w 0..39); computes row pair
// (2q, 2q+1), col w (w<38), all 12 g in 2 chunks of 6. Basis pre-duplicated
// in shared as u64 pairs -> LDS.64/128 broadcast, zero packing in loop.
// Window: 4 rows x 3 cols, row-pair packed f32x2 (no selects).
// Phase B (gather): out = accP[T][I-1][J-1] + bias, coalesced stores.
// ---------------------------------------------------------------------------
__global__ void __launch_bounds__(480, 2)
stage2_kernel(const float* __restrict__ basis, const float* __restrict__ bias,
              const int* __restrict__ Iarr, const int* __restrict__ Jarr,
              const int* __restrict__ Tarr, float* __restrict__ out)
{
    extern __shared__ float smem[];
    float* tsh  = smem;             // 8960 floats: t slice [4 o][7 b][320]
    float* accP = smem + 8960;      // 11520 floats: [12 g][4 oo][6][40]
    __shared__ __align__(16) u64 bas_dup[840];   // [g][b][10] (9 used)
    __shared__ float bias_sh[8];

    const int bid  = blockIdx.x;
    const int v    = bid >> 1;
    const int half = bid & 1;
    const int o0   = half * 4;
    const int tid  = threadIdx.x;

    const int zv = v % 12;
    const int yv = (v / 12) % 12;
    const int xv = v / 144;

    if (xv < 1 || xv > 9 || yv < 1 || yv > 9 || zv < 1 || zv > 9) {
        // border voxel: zero this half's 48 channels (12g x 4o x 320)
        const float4 z = make_float4(0.f, 0.f, 0.f, 0.f);
        for (int i = tid; i < 3840; i += 480) {
            int ch = i / 80;             // 0..47
            int r  = i - ch * 80;
            int g  = ch >> 2;
            int oo = ch & 3;
            float4* p = (float4*)(out + (size_t)(g * 8 + o0 + oo) * 552960
                                      + (size_t)v * 320);
            p[r] = z;
        }
        return;
    }

    const int n = (xv - 1) * 81 + (yv - 1) * 9 + (zv - 1);

    // stage t slice for o0..o0+3 (28 ob rows x 320)
    {
        const float4* src = (const float4*)(g_t + (size_t)n * 17920 + o0 * 2240);
        float4* dst = (float4*)tsh;
        for (int i = tid; i < 2240; i += 480) dst[i] = src[i];
    }
    // duplicated basis: bas_dup[(g*7+b)*10 + j] = (bas, bas)
    for (int i = tid; i < 756; i += 480) {
        int g = i / 63;  int r = i - g * 63;
        int b = r / 9;   int j = r - b * 9;
        float bv = basis[i];
        bas_dup[(g * 7 + b) * 10 + j] = pack2(bv, bv);
    }
    if (tid < 8) {
        float s = 0.f;
        for (int j = 0; j < 27; j++) s += bias[tid * 27 + j];
        bias_sh[tid] = s;
    }
    __syncthreads();

    // ---- Phase A: dense conv ----
    const int oo = tid / 120;
    const int rq = tid - oo * 120;
    const int q  = rq / 40;            // row pair (2q, 2q+1)
    const int w  = rq - q * 40;        // output col j' = w

    if (w < 38) {
#pragma unroll 1
        for (int ch = 0; ch < 2; ch++) {
            u64 acc[6];
#pragma unroll
            for (int gg = 0; gg < 6; gg++) acc[gg] = 0ull;

#pragma unroll 1
            for (int b = 0; b < 7; b++) {
                const float* tb = tsh + (oo * 7 + b) * 320 + q * 80 + w;
                float win[4][3];
#pragma unroll
                for (int j = 0; j < 4; j++)
#pragma unroll
                    for (int vv = 0; vv < 3; vv++)
                        win[j][vv] = tb[j * 40 + vv];
                u64 wp[9];
#pragma unroll
                for (int u = 0; u < 3; u++)
#pragma unroll
                    for (int vv = 0; vv < 3; vv++)
                        wp[u * 3 + vv] = pack2(win[u][vv], win[u + 1][vv]);

#pragma unroll
                for (int gg = 0; gg < 6; gg++) {
                    int g = ch * 6 + gg;
                    const ulonglong2* bp =
                        (const ulonglong2*)(bas_dup + (g * 7 + b) * 10);
                    ulonglong2 b01 = bp[0];
                    ulonglong2 b23 = bp[1];
                    ulonglong2 b45 = bp[2];
                    ulonglong2 b67 = bp[3];
                    u64 b8 = bas_dup[(g * 7 + b) * 10 + 8];
                    ffma2(acc[gg], b01.x, wp[0]);
                    ffma2(acc[gg], b01.y, wp[1]);
                    ffma2(acc[gg], b23.x, wp[2]);
                    ffma2(acc[gg], b23.y, wp[3]);
                    ffma2(acc[gg], b45.x, wp[4]);
                    ffma2(acc[gg], b45.y, wp[5]);
                    ffma2(acc[gg], b67.x, wp[6]);
                    ffma2(acc[gg], b67.y, wp[7]);
                    ffma2(acc[gg], b8,    wp[8]);
                }
            }

#pragma unroll
            for (int gg = 0; gg < 6; gg++) {
                int g = ch * 6 + gg;
                float lo, hi;
                unpack2(acc[gg], lo, hi);
                float* ap = accP + ((g * 4 + oo) * 240) + q * 80 + w;
                ap[0]  = lo;   // row i' = 2q
                ap[40] = hi;   // row i' = 2q+1
            }
        }
    }
    __syncthreads();

    // ---- Phase B: gather + store ----
    // flat = k*480 + tid over [0, 15360): go_l = flat/320, pos = flat%320
    const int p_a  = (tid < 320) ? tid : tid - 320;
    const int p_b  = (p_a + 160 < 320) ? p_a + 160 : p_a - 160;
    const int offa = (Iarr[p_a] - 1) * 40 + (Jarr[p_a] - 1);
    const int offb = (Iarr[p_b] - 1) * 40 + (Jarr[p_b] - 1);

    int go_l = tid / 320;
    int pos  = p_a;
    float* outv = out + (size_t)v * 320;

#pragma unroll 1
    for (int k = 0; k < 32; k++) {
        const int g   = go_l >> 2;
        const int oo2 = go_l & 3;
        const int tg  = Tarr[g * 320 + pos];
        const int ao  = (pos == p_a) ? offa : offb;
        float val = accP[(tg * 4 + oo2) * 240 + ao] + bias_sh[o0 + oo2];
        outv[(size_t)(g * 8 + o0 + oo2) * 552960 + pos] = val;
        // advance flat by 480
        go_l += 1;
        pos  += 160;
        if (pos >= 320) { pos -= 320; go_l += 1; }
    }
}

// ---------------------------------------------------------------------------
extern "C" void kernel_launch(void* const* d_in, const int* in_sizes, int n_in,
                              void* d_out, int out_size)
{
    (void)in_sizes; (void)n_in; (void)out_size;

    const float* x      = (const float*)d_in[0];
    const float* weight = (const float*)d_in[1];
    const float* bias   = (const float*)d_in[2];
    const float* basis  = (const float*)d_in[3];
    const int*   Iarr   = (const int*)d_in[4];
    const int*   Jarr   = (const int*)d_in[5];
    const int*   Tarr   = (const int*)d_in[6];
    float*       out    = (float*)d_out;

    cudaFuncSetAttribute(stage2_kernel,
                         cudaFuncAttributeMaxDynamicSharedMemorySize, 81920);

    stage1_kernel<<<729, 320>>>(x, weight);
    stage2_kernel<<<3456, 480, 81920>>>(basis, bias, Iarr, Jarr, Tarr, out);
}

// round 16
// speedup vs baseline: 1.2142x; 1.0058x over previous
#include <cuda_runtime.h>
#include <cstddef>

// ---------------------------------------------------------------------------
//  B=1, C=8, O=8, G=12, X=Y=Z=12, CH=8, CW=40, Xo=Yo=Zo=9, N=729, GO=96, b=7
//  Stage1: t[n][ob][pos] = sum_{c,f} W[o,c,f,b] * x[c, n+f, pos]
//  Stage2 (gather-last):
//    accP[g][o][i'][j'] = sum_{b,u,v} basis[g,b,u,v] * t[o*7+b][(i'+u)*40 + j'+v]
//    out[g*8+o][v][h,w] = accP[T[g,h,w]][o][I[h,w]-1][J[h,w]-1] + bias_sum[o]
// ---------------------------------------------------------------------------

typedef unsigned long long u64;

#define T_ELEMS (729 * 56 * 320)
__device__ __align__(16) float g_t[T_ELEMS];   // 52.25 MB scratch

__device__ __forceinline__ u64 pack2(float a, float b) {
    u64 r;
    asm("mov.b64 %0, {%1, %2};" : "=l"(r) : "f"(a), "f"(b));
    return r;
}
__device__ __forceinline__ void unpack2(u64 v, float& a, float& b) {
    asm("mov.b64 {%0, %1}, %2;" : "=f"(a), "=f"(b) : "l"(v));
}
__device__ __forceinline__ void ffma2(u64& acc, u64 w, u64 x) {
    asm("fma.rn.f32x2 %0, %1, %2, %0;" : "+l"(acc) : "l"(w), "l"(x));
}

// ---------------------------------------------------------------------------
// Stage 1: one CTA per n (729), 320 threads, one pos each.
// x staged per-f through a double-buffered shared tile (coalesced float4
// LDGs issued at loop top, consumed next iteration -> latency hidden).
// Weights in shared [f][c][ob], read via 128-bit broadcasts.
// Dynamic smem: Wsh 12096 + xsh 2*2560 floats = 68,864 B.
// ---------------------------------------------------------------------------
__global__ void __launch_bounds__(320, 2)
stage1_kernel(const float* __restrict__ x, const float* __restrict__ weight)
{
    extern __shared__ __align__(16) float s1[];
    float* Wsh = s1;                 // 12096 floats
    float* xs0 = s1 + 12096;         // 2560 floats
    float* xs1 = s1 + 12096 + 2560;  // 2560 floats
    __shared__ int off_sh[27];

    const int n   = blockIdx.x;
    const int tid = threadIdx.x;

    // transpose weight: (o,c,f,b) -> [(f*8+c)*56 + o*7 + b]
    for (int i = tid; i < 12096; i += 320) {
        int o = i / 1512;  int r = i - o * 1512;
        int c = r / 189;   r -= c * 189;
        int f = r / 7;     int b = r - f * 7;
        Wsh[(f * 8 + c) * 56 + o * 7 + b] = weight[i];
    }
    if (tid < 27) {
        int fi = tid / 9;  int fr = tid - fi * 9;
        int fj = fr / 3;   int fk = fr - fj * 3;
        off_sh[tid] = fi * 46080 + fj * 3840 + fk * 320;
    }
    __syncthreads();

    const int zi = n % 9;
    const int yi = (n / 9) % 9;
    const int xi = n / 81;
    const float* xv = x + (size_t)xi * 46080 + (size_t)yi * 3840 + (size_t)zi * 320;

    // prefetch lane decomposition: 640 float4 per f-tile, 2 per thread
    const int idx0 = tid;
    const int idx1 = tid + 320;
    const int c0 = idx0 / 80, q0 = (idx0 - c0 * 80) * 4;
    const int c1 = idx1 / 80, q1 = (idx1 - c1 * 80) * 4;

    // load f = 0 (off_sh[0] == 0)
    {
        float4 v0 = *(const float4*)(xv + (size_t)c0 * 552960 + q0);
        float4 v1 = *(const float4*)(xv + (size_t)c1 * 552960 + q1);
        *(float4*)(xs0 + c0 * 320 + q0) = v0;
        *(float4*)(xs0 + c1 * 320 + q1) = v1;
    }
    __syncthreads();

    u64 acc[28];
#pragma unroll
    for (int p = 0; p < 28; p++) acc[p] = 0ull;

    for (int f = 0; f < 27; f++) {
        float* xbuf = (f & 1) ? xs1 : xs0;
        float* xnxt = (f & 1) ? xs0 : xs1;
        const bool pf = (f + 1 < 27);
        float4 v0, v1;
        if (pf) {
            const float* src = xv + off_sh[f + 1];
            v0 = *(const float4*)(src + (size_t)c0 * 552960 + q0);
            v1 = *(const float4*)(src + (size_t)c1 * 552960 + q1);
        }

#pragma unroll
        for (int c = 0; c < 8; c++) {
            float xl = xbuf[c * 320 + tid];
            u64 xx = pack2(xl, xl);
            const ulonglong2* wp = (const ulonglong2*)(Wsh + (f * 8 + c) * 56);
#pragma unroll
            for (int p = 0; p < 14; p++) {
                ulonglong2 ww = wp[p];
                ffma2(acc[2 * p],     ww.x, xx);
                ffma2(acc[2 * p + 1], ww.y, xx);
            }
        }

        if (pf) {
            *(float4*)(xnxt + c0 * 320 + q0) = v0;
            *(float4*)(xnxt + c1 * 320 + q1) = v1;
            __syncthreads();
        }
    }

    float* tp = g_t + (size_t)n * 17920 + tid;
#pragma unroll
    for (int q = 0; q < 28; q++) {
        float lo, hi;
        unpack2(acc[q], lo, hi);
        tp[(2 * q) * 320]     = lo;
        tp[(2 * q + 1) * 320] = hi;
    }
}

// ---------------------------------------------------------------------------
// Stage 2 (gather-last, g-pair packed): grid = 1728 voxels x 2 o-halves,
// 480 threads. Phase A thread = (oo 0..3, row r 0..5, col-pair wp 0..19,
// wp<19 active). f32x2 lanes carry (g even, g odd); basis pre-paired in
// shared -> one u64 LDS covers 2 g. Window 3x4 via float2 (conflict-free).
// g-pairs in 2 chunks of 3 -> 6 u64 accumulators, ~60 regs, no spills.
// Phase B: out = accP[T][I-1][J-1] + bias, coalesced stores.
// ---------------------------------------------------------------------------
__global__ void __launch_bounds__(480, 2)
stage2_kernel(const float* __restrict__ basis, const float* __restrict__ bias,
              const int* __restrict__ Iarr, const int* __restrict__ Jarr,
              const int* __restrict__ Tarr, float* __restrict__ out)
{
    extern __shared__ float smem[];
    float* tsh  = smem;             // 8960 floats: t slice [4 o][7 b][320]
    float* accP = smem + 8960;      // 11520 floats: [12 g][4 oo][6][40]
    __shared__ __align__(16) u64 bas_pair[420];  // [gp*7+b][10] (9 used)
    __shared__ float bias_sh[8];

    const int bid  = blockIdx.x;
    const int v    = bid >> 1;
    const int half = bid & 1;
    const int o0   = half * 4;
    const int tid  = threadIdx.x;

    const int zv = v % 12;
    const int yv = (v / 12) % 12;
    const int xv = v / 144;

    if (xv < 1 || xv > 9 || yv < 1 || yv > 9 || zv < 1 || zv > 9) {
        const float4 z = make_float4(0.f, 0.f, 0.f, 0.f);
        for (int i = tid; i < 3840; i += 480) {
            int ch = i / 80;
            int r  = i - ch * 80;
            int g  = ch >> 2;
            int oo = ch & 3;
            float4* p = (float4*)(out + (size_t)(g * 8 + o0 + oo) * 552960
                                      + (size_t)v * 320);
            p[r] = z;
        }
        return;
    }

    const int n = (xv - 1) * 81 + (yv - 1) * 9 + (zv - 1);

    {
        const float4* src = (const float4*)(g_t + (size_t)n * 17920 + o0 * 2240);
        float4* dst = (float4*)tsh;
        for (int i = tid; i < 2240; i += 480) dst[i] = src[i];
    }
    // paired basis: lane-lo = g even, lane-hi = g odd
    for (int i = tid; i < 378; i += 480) {
        int gp = i / 63;  int r = i - gp * 63;
        int b  = r / 9;   int j = r - b * 9;
        float b0 = basis[(2 * gp) * 63 + b * 9 + j];
        float b1 = basis[(2 * gp + 1) * 63 + b * 9 + j];
        bas_pair[(gp * 7 + b) * 10 + j] = pack2(b0, b1);
    }
    if (tid < 8) {
        float s = 0.f;
        for (int j = 0; j < 27; j++) s += bias[tid * 27 + j];
        bias_sh[tid] = s;
    }
    __syncthreads();

    // ---- Phase A: dense conv, g-pair packed ----
    const int oo = tid / 120;
    const int rr = tid - oo * 120;
    const int r  = rr / 20;            // output row i' = r (0..5)
    const int wp = rr - r * 20;        // col pair
    const int w0 = wp * 2;

    if (wp < 19) {
#pragma unroll 1
        for (int ch = 0; ch < 2; ch++) {
            u64 acc0[3], acc1[3];      // [gp_local] for col w0, w0+1
#pragma unroll
            for (int gl = 0; gl < 3; gl++) { acc0[gl] = 0ull; acc1[gl] = 0ull; }

#pragma unroll 1
            for (int b = 0; b < 7; b++) {
                const float* tb = tsh + (oo * 7 + b) * 320 + r * 40 + w0;
                // 3x4 window via float2 (aligned: all offsets even)
                u64 wd[3][4];
#pragma unroll
                for (int u = 0; u < 3; u++) {
                    float2 ab = *(const float2*)(tb + u * 40);
                    float2 cd = *(const float2*)(tb + u * 40 + 2);
                    wd[u][0] = pack2(ab.x, ab.x);
                    wd[u][1] = pack2(ab.y, ab.y);
                    wd[u][2] = pack2(cd.x, cd.x);
                    wd[u][3] = pack2(cd.y, cd.y);
                }

#pragma unroll
                for (int gl = 0; gl < 3; gl++) {
                    int gp = ch * 3 + gl;
                    const ulonglong2* bp =
                        (const ulonglong2*)(bas_pair + (gp * 7 + b) * 10);
                    ulonglong2 b01 = bp[0];
                    ulonglong2 b23 = bp[1];
                    ulonglong2 b45 = bp[2];
                    ulonglong2 b67 = bp[3];
                    u64 b8 = bas_pair[(gp * 7 + b) * 10 + 8];
                    // col 0
                    ffma2(acc0[gl], b01.x, wd[0][0]);
                    ffma2(acc0[gl], b01.y, wd[0][1]);
                    ffma2(acc0[gl], b23.x, wd[0][2]);
                    ffma2(acc0[gl], b23.y, wd[1][0]);
                    ffma2(acc0[gl], b45.x, wd[1][1]);
                    ffma2(acc0[gl], b45.y, wd[1][2]);
                    ffma2(acc0[gl], b67.x, wd[2][0]);
                    ffma2(acc0[gl], b67.y, wd[2][1]);
                    ffma2(acc0[gl], b8,    wd[2][2]);
                    // col 1 (shift v by 1)
                    ffma2(acc1[gl], b01.x, wd[0][1]);
                    ffma2(acc1[gl], b01.y, wd[0][2]);
                    ffma2(acc1[gl], b23.x, wd[0][3]);
                    ffma2(acc1[gl], b23.y, wd[1][1]);
                    ffma2(acc1[gl], b45.x, wd[1][2]);
                    ffma2(acc1[gl], b45.y, wd[1][3]);
                    ffma2(acc1[gl], b67.x, wd[2][1]);
                    ffma2(acc1[gl], b67.y, wd[2][2]);
                    ffma2(acc1[gl], b8,    wd[2][3]);
                }
            }

#pragma unroll
            for (int gl = 0; gl < 3; gl++) {
                int g0 = 2 * (ch * 3 + gl);
                float e0, o0v, e1, o1v;
                unpack2(acc0[gl], e0, o0v);
                unpack2(acc1[gl], e1, o1v);
                float* apE = accP + ((g0 * 4 + oo) * 240) + r * 40 + w0;
                float* apO = accP + (((g0 + 1) * 4 + oo) * 240) + r * 40 + w0;
                apE[0] = e0;  apE[1] = e1;
                apO[0] = o0v; apO[1] = o1v;
            }
        }
    }
    __syncthreads();

    // ---- Phase B: gather + store ----
    const int p_a  = (tid < 320) ? tid : tid - 320;
    const int p_b  = (p_a + 160 < 320) ? p_a + 160 : p_a - 160;
    const int offa = (Iarr[p_a] - 1) * 40 + (Jarr[p_a] - 1);
    const int offb = (Iarr[p_b] - 1) * 40 + (Jarr[p_b] - 1);

    int go_l = tid / 320;
    int pos  = p_a;
    float* outv = out + (size_t)v * 320;

#pragma unroll 1
    for (int k = 0; k < 32; k++) {
        const int g   = go_l >> 2;
        const int oo2 = go_l & 3;
        const int tg  = Tarr[g * 320 + pos];
        const int ao  = (pos == p_a) ? offa : offb;
        float val = accP[(tg * 4 + oo2) * 240 + ao] + bias_sh[o0 + oo2];
        outv[(size_t)(g * 8 + o0 + oo2) * 552960 + pos] = val;
        go_l += 1;
        pos  += 160;
        if (pos >= 320) { pos -= 320; go_l += 1; }
    }
}

// ---------------------------------------------------------------------------
extern "C" void kernel_launch(void* const* d_in, const int* in_sizes, int n_in,
                              void* d_out, int out_size)
{
    (void)in_sizes; (void)n_in; (void)out_size;

    const float* x      = (const float*)d_in[0];
    const float* weight = (const float*)d_in[1];
    const float* bias   = (const float*)d_in[2];
    const float* basis  = (const float*)d_in[3];
    const int*   Iarr   = (const int*)d_in[4];
    const int*   Jarr   = (const int*)d_in[5];
    const int*   Tarr   = (const int*)d_in[6];
    float*       out    = (float*)d_out;

    cudaFuncSetAttribute(stage1_kernel,
                         cudaFuncAttributeMaxDynamicSharedMemorySize, 68864);
    cudaFuncSetAttribute(stage2_kernel,
                         cudaFuncAttributeMaxDynamicSharedMemorySize, 81920);

    stage1_kernel<<<729, 320, 68864>>>(x, weight);
    stage2_kernel<<<3456, 480, 81920>>>(basis, bias, Iarr, Jarr, Tarr, out);
}

// round 17
// speedup vs baseline: 1.2840x; 1.0575x over previous
#include <cuda_runtime.h>
#include <cstddef>

// ---------------------------------------------------------------------------
//  B=1, C=8, O=8, G=12, X=Y=Z=12, CH=8, CW=40, Xo=Yo=Zo=9, N=729, GO=96, b=7
//  Stage1: t[n][ob][pos] = sum_{c,f} W[o,c,f,b] * x[c, n+f, pos]
//  Stage2 (gather-last):
//    accP[g][o][i'][j'] = sum_{b,u,v} basis[g,b,u,v] * t[o*7+b][(i'+u)*40 + j'+v]
//    out[g*8+o][v][h,w] = accP[T[g,h,w]][o][I[h,w]-1][J[h,w]-1] + bias_sum[o]
// ---------------------------------------------------------------------------

typedef unsigned long long u64;

#define T_ELEMS (729 * 56 * 320)
__device__ __align__(16) float g_t[T_ELEMS];   // 52.25 MB scratch

__device__ __forceinline__ u64 pack2(float a, float b) {
    u64 r;
    asm("mov.b64 %0, {%1, %2};" : "=l"(r) : "f"(a), "f"(b));
    return r;
}
__device__ __forceinline__ void unpack2(u64 v, float& a, float& b) {
    asm("mov.b64 {%0, %1}, %2;" : "=f"(a), "=f"(b) : "l"(v));
}
__device__ __forceinline__ void ffma2(u64& acc, u64 w, u64 x) {
    asm("fma.rn.f32x2 %0, %1, %2, %0;" : "+l"(acc) : "l"(w), "l"(x));
}

// ---------------------------------------------------------------------------
// Stage 1: grid = 729 n x 2 ob-halves, 320 threads, one pos each.
// Each CTA computes 28 of the 56 ob rows: 14 f32x2 accumulators (28 regs),
// 7 LDS.128 weight broadcasts per (c,f) -> enough registers to pipeline.
// 24 KB smem -> 3 CTAs/SM (7.5 warps/SMSP) hides LDS/LDG latency.
// ---------------------------------------------------------------------------
__global__ void __launch_bounds__(320, 3)
stage1_kernel(const float* __restrict__ x, const float* __restrict__ weight)
{
    __shared__ __align__(16) float Wsh[6048];   // [(c*27+f)*28 + o'*7 + b]
    __shared__ int off_sh[216];

    const int bid = blockIdx.x;
    const int n   = bid >> 1;
    const int obh = bid & 1;          // ob-half: rows obh*28 .. obh*28+27
    const int tid = threadIdx.x;

    // load this half's weights transposed: (o0+o',c,f,b) -> [(c*27+f)*28 + o'*7+b]
    for (int i = tid; i < 6048; i += 320) {
        int op = i / 1512;  int r = i - op * 1512;
        int c  = r / 189;   r -= c * 189;
        int f  = r / 7;     int b = r - f * 7;
        Wsh[(c * 27 + f) * 28 + op * 7 + b] =
            weight[(obh * 4 + op) * 1512 + c * 189 + f * 7 + b];
    }
    if (tid < 216) {
        int c  = tid / 27;  int f  = tid - c * 27;
        int fi = f / 9;     int fr = f - fi * 9;
        int fj = fr / 3;    int fk = fr - fj * 3;
        off_sh[tid] = c * 552960 + fi * 46080 + fj * 3840 + fk * 320;
    }
    __syncthreads();

    const int zi = n % 9;
    const int yi = (n / 9) % 9;
    const int xi = n / 81;
    const float* xb = x + (size_t)xi * 46080 + (size_t)yi * 3840 + (size_t)zi * 320 + tid;

    u64 acc[14];
#pragma unroll
    for (int p = 0; p < 14; p++) acc[p] = 0ull;

    // depth-2 scalar prefetch of x
    float a_c = xb[0];
    float a_n = xb[off_sh[1]];

    for (int cf = 0; cf < 216; cf++) {
        float a_2 = 0.f;
        if (cf + 2 < 216) a_2 = xb[off_sh[cf + 2]];

        u64 xx = pack2(a_c, a_c);
        const ulonglong2* wp = (const ulonglong2*)(Wsh + cf * 28);
#pragma unroll
        for (int p = 0; p < 7; p++) {
            ulonglong2 ww = wp[p];
            ffma2(acc[2 * p],     ww.x, xx);
            ffma2(acc[2 * p + 1], ww.y, xx);
        }
        a_c = a_n;
        a_n = a_2;
    }

    float* tp = g_t + (size_t)n * 17920 + obh * 8960 + tid;
#pragma unroll
    for (int q = 0; q < 14; q++) {
        float lo, hi;
        unpack2(acc[q], lo, hi);
        tp[(2 * q) * 320]     = lo;   // ob' = 2q
        tp[(2 * q + 1) * 320] = hi;   // ob' = 2q+1
    }
}

// ---------------------------------------------------------------------------
// Stage 2 (gather-last, g-pair packed, b-outer): grid = 1728 voxels x 2
// o-halves, 480 threads. Phase A thread = (oo 0..3, row r 0..5, col-pair wp).
// f32x2 lanes = (g even, g odd); all 6 g-pair accumulators live across the
// b loop so the 3x4 window is loaded ONCE per b (6 LDS.64 + 12 packs),
// shared by all 12 g. Basis pre-paired in shared (5 LDS per (gp,b)).
// Phase B: out = accP[T][I-1][J-1] + bias, coalesced stores.
// ---------------------------------------------------------------------------
__global__ void __launch_bounds__(480, 2)
stage2_kernel(const float* __restrict__ basis, const float* __restrict__ bias,
              const int* __restrict__ Iarr, const int* __restrict__ Jarr,
              const int* __restrict__ Tarr, float* __restrict__ out)
{
    extern __shared__ float smem[];
    float* tsh  = smem;             // 8960 floats: t slice [4 o][7 b][320]
    float* accP = smem + 8960;      // 11520 floats: [12 g][4 oo][6][40]
    __shared__ __align__(16) u64 bas_pair[420];  // [gp*7+b][10] (9 used)
    __shared__ float bias_sh[8];

    const int bid  = blockIdx.x;
    const int v    = bid >> 1;
    const int half = bid & 1;
    const int o0   = half * 4;
    const int tid  = threadIdx.x;

    const int zv = v % 12;
    const int yv = (v / 12) % 12;
    const int xv = v / 144;

    if (xv < 1 || xv > 9 || yv < 1 || yv > 9 || zv < 1 || zv > 9) {
        const float4 z = make_float4(0.f, 0.f, 0.f, 0.f);
        for (int i = tid; i < 3840; i += 480) {
            int ch = i / 80;
            int r  = i - ch * 80;
            int g  = ch >> 2;
            int oo = ch & 3;
            float4* p = (float4*)(out + (size_t)(g * 8 + o0 + oo) * 552960
                                      + (size_t)v * 320);
            p[r] = z;
        }
        return;
    }

    const int n = (xv - 1) * 81 + (yv - 1) * 9 + (zv - 1);

    {
        const float4* src = (const float4*)(g_t + (size_t)n * 17920 + o0 * 2240);
        float4* dst = (float4*)tsh;
        for (int i = tid; i < 2240; i += 480) dst[i] = src[i];
    }
    // paired basis: lane-lo = g even, lane-hi = g odd
    for (int i = tid; i < 378; i += 480) {
        int gp = i / 63;  int r = i - gp * 63;
        int b  = r / 9;   int j = r - b * 9;
        float b0 = basis[(2 * gp) * 63 + b * 9 + j];
        float b1 = basis[(2 * gp + 1) * 63 + b * 9 + j];
        bas_pair[(gp * 7 + b) * 10 + j] = pack2(b0, b1);
    }
    if (tid < 8) {
        float s = 0.f;
        for (int j = 0; j < 27; j++) s += bias[tid * 27 + j];
        bias_sh[tid] = s;
    }
    __syncthreads();

    // ---- Phase A: dense conv, g-pair packed, windows hoisted over g ----
    const int oo = tid / 120;
    const int rr = tid - oo * 120;
    const int r  = rr / 20;            // output row i' = r (0..5)
    const int wp = rr - r * 20;        // col pair
    const int w0 = wp * 2;

    if (wp < 19) {
        u64 acc[6][2];                 // [gp][col] -- all 12 live (24 regs)
#pragma unroll
        for (int gl = 0; gl < 6; gl++) { acc[gl][0] = 0ull; acc[gl][1] = 0ull; }

#pragma unroll 1
        for (int b = 0; b < 7; b++) {
            const float* tb = tsh + (oo * 7 + b) * 320 + r * 40 + w0;
            // 3x4 window via float2 (aligned: all offsets even), dup-packed
            u64 wd[3][4];
#pragma unroll
            for (int u = 0; u < 3; u++) {
                float2 ab = *(const float2*)(tb + u * 40);
                float2 cd = *(const float2*)(tb + u * 40 + 2);
                wd[u][0] = pack2(ab.x, ab.x);
                wd[u][1] = pack2(ab.y, ab.y);
                wd[u][2] = pack2(cd.x, cd.x);
                wd[u][3] = pack2(cd.y, cd.y);
            }

#pragma unroll
            for (int gp = 0; gp < 6; gp++) {
                const ulonglong2* bp =
                    (const ulonglong2*)(bas_pair + (gp * 7 + b) * 10);
                ulonglong2 b01 = bp[0];
                ulonglong2 b23 = bp[1];
                ulonglong2 b45 = bp[2];
                ulonglong2 b67 = bp[3];
                u64 b8 = bas_pair[(gp * 7 + b) * 10 + 8];
                // col 0
                ffma2(acc[gp][0], b01.x, wd[0][0]);
                ffma2(acc[gp][0], b01.y, wd[0][1]);
                ffma2(acc[gp][0], b23.x, wd[0][2]);
                ffma2(acc[gp][0], b23.y, wd[1][0]);
                ffma2(acc[gp][0], b45.x, wd[1][1]);
                ffma2(acc[gp][0], b45.y, wd[1][2]);
                ffma2(acc[gp][0], b67.x, wd[2][0]);
                ffma2(acc[gp][0], b67.y, wd[2][1]);
                ffma2(acc[gp][0], b8,    wd[2][2]);
                // col 1 (shift v by 1)
                ffma2(acc[gp][1], b01.x, wd[0][1]);
                ffma2(acc[gp][1], b01.y, wd[0][2]);
                ffma2(acc[gp][1], b23.x, wd[0][3]);
                ffma2(acc[gp][1], b23.y, wd[1][1]);
                ffma2(acc[gp][1], b45.x, wd[1][2]);
                ffma2(acc[gp][1], b45.y, wd[1][3]);
                ffma2(acc[gp][1], b67.x, wd[2][1]);
                ffma2(acc[gp][1], b67.y, wd[2][2]);
                ffma2(acc[gp][1], b8,    wd[2][3]);
            }
        }

#pragma unroll
        for (int gp = 0; gp < 6; gp++) {
            int g0 = 2 * gp;
            float e0, ov0, e1, ov1;
            unpack2(acc[gp][0], e0, ov0);
            unpack2(acc[gp][1], e1, ov1);
            float* apE = accP + ((g0 * 4 + oo) * 240) + r * 40 + w0;
            float* apO = accP + (((g0 + 1) * 4 + oo) * 240) + r * 40 + w0;
            apE[0] = e0;  apE[1] = e1;
            apO[0] = ov0; apO[1] = ov1;
        }
    }
    __syncthreads();

    // ---- Phase B: gather + store ----
    const int p_a  = (tid < 320) ? tid : tid - 320;
    const int p_b  = (p_a + 160 < 320) ? p_a + 160 : p_a - 160;
    const int offa = (Iarr[p_a] - 1) * 40 + (Jarr[p_a] - 1);
    const int offb = (Iarr[p_b] - 1) * 40 + (Jarr[p_b] - 1);

    int go_l = tid / 320;
    int pos  = p_a;
    float* outv = out + (size_t)v * 320;

#pragma unroll 1
    for (int k = 0; k < 32; k++) {
        const int g   = go_l >> 2;
        const int oo2 = go_l & 3;
        const int tg  = Tarr[g * 320 + pos];
        const int ao  = (pos == p_a) ? offa : offb;
        float val = accP[(tg * 4 + oo2) * 240 + ao] + bias_sh[o0 + oo2];
        outv[(size_t)(g * 8 + o0 + oo2) * 552960 + pos] = val;
        go_l += 1;
        pos  += 160;
        if (pos >= 320) { pos -= 320; go_l += 1; }
    }
}

// ---------------------------------------------------------------------------
extern "C" void kernel_launch(void* const* d_in, const int* in_sizes, int n_in,
                              void* d_out, int out_size)
{
    (void)in_sizes; (void)n_in; (void)out_size;

    const float* x      = (const float*)d_in[0];
    const float* weight = (const float*)d_in[1];
    const float* bias   = (const float*)d_in[2];
    const float* basis  = (const float*)d_in[3];
    const int*   Iarr   = (const int*)d_in[4];
    const int*   Jarr   = (const int*)d_in[5];
    const int*   Tarr   = (const int*)d_in[6];
    float*       out    = (float*)d_out;

    cudaFuncSetAttribute(stage2_kernel,
                         cudaFuncAttributeMaxDynamicSharedMemorySize, 81920);

    stage1_kernel<<<1458, 320>>>(x, weight);
    stage2_kernel<<<3456, 480, 81920>>>(basis, bias, Iarr, Jarr, Tarr, out);
}